// round 9
// baseline (speedup 1.0000x reference)
#include <cuda_runtime.h>

// NAM_42442866819214 — ONE fused kernel, low-pressure spin.
// (R7's fused version was 17us IN-KERNEL because 512 blocks polled the flag
//  line every 32ns — LTS slice saturation starved the publishers' atomics.
//  Fix: single go-flag, ld.global.cg polls with exponential backoff.)
//
// Math collapse (per-feature, valid when b1[f,:]==0 && b2[f,:]==0, verified
// at runtime into g_mode[f]):
//   relu(x*w) = x * (x>0 ? max(w,0) : min(w,0))
//   contrib(b,f) = x * (x>0 ? dpos[f] : dneg[f]) + b3[f]
//
// 512 blocks x 256 thr (<=64 regs -> 4/SM -> all wave-1 resident):
//   every block : prefetch its 16 input rows + b3 + bias FIRST
//   blocks 0-127: fold W1,W2,W3 -> dpos/dneg for one feature (8-way split),
//                 publish, atomicAdd(g_ready); the 128th sets g_go=1
//   every block : tid0 polls g_go (cg load, 128ns->2us backoff), syncthreads
//   every block : piecewise-linear map, store contribs, row sums
//   last block  : resets g_ready/g_done/g_go (graph-replay deterministic)

#define NB   8192
#define NF   128
#define NH1  64
#define NH2  32
#define GRID 512
#define RPB  16    // rows per block = 8 warps * 2 rows

__device__ float g_dpos[NF];
__device__ float g_dneg[NF];
__device__ int   g_mode[NF];
__device__ int   g_ready;   // publisher count
__device__ int   g_go;      // release flag
__device__ int   g_done;    // completion count (for reset)

__device__ __forceinline__ int ld_cg(const int* p) {
    int v;
    asm volatile("ld.global.cg.s32 %0, [%1];" : "=r"(v) : "l"(p) : "memory");
    return v;
}

// Dead unless b1/b2 nonzero; kept for correctness on arbitrary bias values.
__device__ __noinline__ float mlp_full(float x, int f,
                                       const float* __restrict__ W1,
                                       const float* __restrict__ b1,
                                       const float* __restrict__ W2,
                                       const float* __restrict__ b2,
                                       const float* __restrict__ W3) {
    float acc = 0.f;
    for (int k = 0; k < NH2; k++) {
        float a = b2[f * NH2 + k];
        for (int i = 0; i < NH1; i++) {
            float h1 = fmaxf(fmaf(x, W1[f * NH1 + i], b1[f * NH1 + i]), 0.f);
            a = fmaf(h1, W2[(f * NH1 + i) * NH2 + k], a);
        }
        acc = fmaf(fmaxf(a, 0.f), W3[f * NH2 + k], acc);
    }
    return acc;
}

__global__ void __launch_bounds__(256, 4)
nam_fused(const float* __restrict__ inputs,
          const float* __restrict__ W1,
          const float* __restrict__ b1,
          const float* __restrict__ W2,
          const float* __restrict__ b2,
          const float* __restrict__ W3,
          const float* __restrict__ b3,
          const float* __restrict__ bias,
          float* __restrict__ out) {
    const int tid  = threadIdx.x;
    const int lane = tid & 31;
    const int warp = tid >> 5;           // 0..7
    const int b0   = blockIdx.x * RPB + warp;
    const int f0   = lane * 4;

    const float4* in4 = (const float4*)inputs;
    float4*       c4  = (float4*)(out + NB);

    // ---- prefetch (independent of precompute) — issue FIRST --------------
    float4 x0 = in4[b0 * (NF / 4) + lane];
    float4 x1 = in4[(b0 + 8) * (NF / 4) + lane];
    const float4 b34   = ((const float4*)b3)[lane];
    const float  bias0 = bias[0];

    // ---- precompute (blocks 0..127, one feature each) --------------------
    __shared__ float s_cp[8][32], s_cn[8][32];
    __shared__ int   s_nz[8];
    if (blockIdx.x < NF) {
        const int f = blockIdx.x;
        const int k = lane;

        int nz = 0;
        if (tid < NH1)            nz = (b1[f * NH1 + tid] != 0.f);
        else if (tid < NH1 + NH2) nz = (b2[f * NH2 + tid - NH1] != 0.f);
        int wnz = __ballot_sync(0xffffffffu, nz) ? 1 : 0;  // all lanes execute

        float cp = 0.f, cn = 0.f;
#pragma unroll
        for (int j = 0; j < 8; j++) {
            const int i = warp * 8 + j;
            float w  = W1[f * NH1 + i];               // warp-uniform
            float w2 = W2[(f * NH1 + i) * NH2 + k];   // coalesced
            cp = fmaf(w2, fmaxf(w, 0.f), cp);
            cn = fmaf(w2, fminf(w, 0.f), cn);
        }
        s_cp[warp][k] = cp;
        s_cn[warp][k] = cn;
        if (lane == 0) s_nz[warp] = wnz;
        __syncthreads();

        if (warp == 0) {
            float tcp = 0.f, tcn = 0.f;
#pragma unroll
            for (int w8 = 0; w8 < 8; w8++) {
                tcp += s_cp[w8][k];
                tcn += s_cn[w8][k];
            }
            float w3 = W3[f * NH2 + k];
            float dp = w3 * fmaxf(tcp, 0.f);
            float dn = w3 * fminf(tcn, 0.f);
#pragma unroll
            for (int o = 16; o > 0; o >>= 1) {
                dp += __shfl_xor_sync(0xffffffffu, dp, o);
                dn += __shfl_xor_sync(0xffffffffu, dn, o);
            }
            if (k == 0) {
                g_dpos[f] = dp;
                g_dneg[f] = dn;
                g_mode[f] = s_nz[0] | s_nz[1] | s_nz[2] | s_nz[3] |
                            s_nz[4] | s_nz[5] | s_nz[6] | s_nz[7];
                __threadfence();
                if (atomicAdd(&g_ready, 1) == NF - 1) {
                    atomicExch(&g_go, 1);      // release everyone
                }
            }
        }
    }

    // ---- low-pressure wait for release ------------------------------------
    if (tid == 0) {
        if (ld_cg(&g_go) == 0) {
            unsigned ns = 128;
            do {
                __nanosleep(ns);
                if (ns < 2048) ns <<= 1;
            } while (ld_cg(&g_go) == 0);
        }
    }
    __syncthreads();

    // ---- stream ------------------------------------------------------------
    const float4 dp4 = __ldcg(&((const float4*)g_dpos)[lane]);
    const float4 dn4 = __ldcg(&((const float4*)g_dneg)[lane]);
    const int4   m4  = __ldcg(&((const int4*)g_mode)[lane]);
    const bool fast = (m4.x | m4.y | m4.z | m4.w) == 0;

#pragma unroll
    for (int r = 0; r < 2; r++) {
        const int b = b0 + r * 8;
        const float4 x = r ? x1 : x0;
        float4 c;
        if (fast) {
            c.x = fmaf(x.x, (x.x > 0.f ? dp4.x : dn4.x), b34.x);
            c.y = fmaf(x.y, (x.y > 0.f ? dp4.y : dn4.y), b34.y);
            c.z = fmaf(x.z, (x.z > 0.f ? dp4.z : dn4.z), b34.z);
            c.w = fmaf(x.w, (x.w > 0.f ? dp4.w : dn4.w), b34.w);
        } else {
            c.x = mlp_full(x.x, f0 + 0, W1, b1, W2, b2, W3) + b34.x;
            c.y = mlp_full(x.y, f0 + 1, W1, b1, W2, b2, W3) + b34.y;
            c.z = mlp_full(x.z, f0 + 2, W1, b1, W2, b2, W3) + b34.z;
            c.w = mlp_full(x.w, f0 + 3, W1, b1, W2, b2, W3) + b34.w;
        }
        c4[b * (NF / 4) + lane] = c;

        float s = (c.x + c.y) + (c.z + c.w);
#pragma unroll
        for (int o = 16; o > 0; o >>= 1)
            s += __shfl_xor_sync(0xffffffffu, s, o);
        if (lane == 0) out[b] = s + bias0;
    }

    // ---- reset counters so every graph replay starts clean -----------------
    __syncthreads();
    if (tid == 0) {
        if (atomicAdd(&g_done, 1) == GRID - 1) {
            g_ready = 0;
            g_go    = 0;
            g_done  = 0;
            __threadfence();
        }
    }
}

extern "C" void kernel_launch(void* const* d_in, const int* in_sizes, int n_in,
                              void* d_out, int out_size) {
    const float* inputs = (const float*)d_in[0];
    const float* W1     = (const float*)d_in[1];
    const float* b1     = (const float*)d_in[2];
    const float* W2     = (const float*)d_in[3];
    const float* b2     = (const float*)d_in[4];
    const float* W3     = (const float*)d_in[5];
    const float* b3     = (const float*)d_in[6];
    const float* bias   = (const float*)d_in[7];

    nam_fused<<<GRID, 256>>>(inputs, W1, b1, W2, b2, W3, b3, bias,
                             (float*)d_out);
}